// round 8
// baseline (speedup 1.0000x reference)
#include <cuda_runtime.h>
#include <math.h>

// ---------------------------------------------------------------------------
// Differentiable JPEG (quality 80) forward pass, fused single kernel.
// Tile = 64x16 px, CTA = 128 threads, each thread owns ONE 8-px row strip.
//   Y (16 blocks): row-DCT in regs -> sY coef columns -> in-place column
//   pass (fwd+quant+inv) -> inverse row-DCT in regs at writeback.
//   Chroma (4 Cb + 4 Cr): 2x2 averaging via shfl_xor(8) vertical pairing +
//   shfl_xor(1) horizontal gather; row-DCT done IN REGISTERS in E1 by the
//   (even sx, even row) threads, so E2 is a perfectly balanced Y-only pass.
// __launch_bounds__(128,14) forces <=36 regs for ~87% occupancy.
// ---------------------------------------------------------------------------

#define IMG 512

__constant__ float c_YTAB[64] = {
    16,11,10,16,24,40,51,61,  12,12,14,19,26,58,60,55,
    14,13,16,24,40,57,69,56,  14,17,22,29,51,87,80,62,
    18,22,37,56,68,109,103,77, 24,35,55,64,81,104,113,92,
    49,64,78,87,103,121,120,101, 72,92,95,98,112,100,103,99};
__constant__ float c_CTAB[64] = {
    17,18,24,47,99,99,99,99,  18,21,26,66,99,99,99,99,
    24,26,56,99,99,99,99,99,  47,66,99,99,99,99,99,99,
    99,99,99,99,99,99,99,99,  99,99,99,99,99,99,99,99,
    99,99,99,99,99,99,99,99,  99,99,99,99,99,99,99,99};

// cos(k*pi/16)
#define C1 0.980785280403230449f
#define C2 0.923879532511286756f
#define C3 0.831469612302545237f
#define C4 0.707106781186547524f
#define C5 0.555570233019602225f
#define C6 0.382683432365089772f
#define C7 0.195090322016128268f

__device__ __forceinline__ void dct8_fwd(const float in[8], float a[8]) {
    float s0 = in[0] + in[7], s1 = in[1] + in[6];
    float s2 = in[2] + in[5], s3 = in[3] + in[4];
    float d0 = in[0] - in[7], d1 = in[1] - in[6];
    float d2 = in[2] - in[5], d3 = in[3] - in[4];
    a[0] = (s0 + s3) + (s1 + s2);
    a[2] = C2 * s0 + C6 * s1 - C6 * s2 - C2 * s3;
    a[4] = C4 * ((s0 + s3) - (s1 + s2));
    a[6] = C6 * s0 - C2 * s1 + C2 * s2 - C6 * s3;
    a[1] = C1 * d0 + C3 * d1 + C5 * d2 + C7 * d3;
    a[3] = C3 * d0 - C7 * d1 - C1 * d2 - C5 * d3;
    a[5] = C5 * d0 - C1 * d1 + C7 * d2 + C3 * d3;
    a[7] = C7 * d0 - C5 * d1 + C3 * d2 - C1 * d3;
}

__device__ __forceinline__ void dct8_inv(const float h[8], float p[8]) {
    float e0 = h[0] + C2 * h[2] + C4 * h[4] + C6 * h[6];
    float e1 = h[0] + C6 * h[2] - C4 * h[4] - C2 * h[6];
    float e2 = h[0] - C6 * h[2] - C4 * h[4] + C2 * h[6];
    float e3 = h[0] - C2 * h[2] + C4 * h[4] - C6 * h[6];
    float o0 = C1 * h[1] + C3 * h[3] + C5 * h[5] + C7 * h[7];
    float o1 = C3 * h[1] - C7 * h[3] - C1 * h[5] - C5 * h[7];
    float o2 = C5 * h[1] - C1 * h[3] + C7 * h[5] + C3 * h[7];
    float o3 = C7 * h[1] - C5 * h[3] + C3 * h[5] - C1 * h[7];
    p[0] = e0 + o0;  p[7] = e0 - o0;
    p[1] = e1 + o1;  p[6] = e1 - o1;
    p[2] = e2 + o2;  p[5] = e2 - o2;
    p[3] = e3 + o3;  p[4] = e3 - o3;
}

__global__ void __launch_bounds__(128, 14)
jpeg_tile_kernel(const float* __restrict__ img, float* __restrict__ out) {
    __shared__ float sY[16 * 72];   // 16 Y blocks, [8][9] per block
    __shared__ float sC[8 * 72];    // 4 Cb + 4 Cr blocks, in-place
    __shared__ float sAqTY[64], sBqTY[64];  // Y quant, transposed [v][u]
    __shared__ float sAqTC[64], sBqTC[64];  // chroma quant, transposed [v][u]

    const int t = threadIdx.x;

    if (t < 64) {
        int u = t >> 3, v = t & 7;
        float au = (u == 0) ? 0.70710678118654752f : 1.f;
        float av = (v == 0) ? 0.70710678118654752f : 1.f;
        float S = au * av * 0.25f;
        float qy = c_YTAB[t] * 0.4f;   // QUALITY=80 -> FACTOR=0.4
        float qc = c_CTAB[t] * 0.4f;
        sAqTY[v * 8 + u] = __fdividef(S, qy);  sBqTY[v * 8 + u] = S * qy;
        sAqTC[v * 8 + u] = __fdividef(S, qc);  sBqTC[v * 8 + u] = S * qc;
    }

    const int bid  = blockIdx.x;
    const int tx   = bid & 7;            // 8 tiles across (64 px)
    const int ty   = (bid >> 3) & 31;    // 32 tiles down (16 px)
    const int bimg = bid >> 8;

    const int sx  = t & 7;               // strip x (8 strips of 8 px)
    const int row = t >> 3;              // tile row 0..15
    const int px0 = tx * 64 + sx * 8;
    const int py0 = ty * 16 + row;

    const size_t plane = (size_t)IMG * IMG;
    const float* base = img + (size_t)bimg * 3 * plane + (size_t)py0 * IMG + px0;

    const int yb    = ((row >> 3) << 3) + sx;   // Y block (8 across, 2 down)
    const int ysw   = yb & 4;
    const int ybase = yb * 72 + (row & 7) * 9;

    // ---- E1: load row, RGB->Y (-128 folded), chroma partials, row-DCT.
    float y[8], cbp[4], crp[4];
    {
        float4 R0 = *(const float4*)(base);
        float4 G0 = *(const float4*)(base + plane);
        float4 B0 = *(const float4*)(base + 2 * plane);
        float Ra[4] = {R0.x, R0.y, R0.z, R0.w};
        float Ga[4] = {G0.x, G0.y, G0.z, G0.w};
        float Ba[4] = {B0.x, B0.y, B0.z, B0.w};
        #pragma unroll
        for (int c = 0; c < 4; c++) {
            float rr = Ra[c] * 255.f, gg = Ga[c] * 255.f, bb = Ba[c] * 255.f;
            y[c] = 0.299f * rr + 0.587f * gg + 0.114f * bb - 128.f;
            float cbv = -0.168736f * rr - 0.331264f * gg + 0.5f      * bb;
            float crv =  0.5f      * rr - 0.418688f * gg - 0.081312f * bb;
            if ((c & 1) == 0) { cbp[c >> 1] = cbv;  crp[c >> 1] = crv; }
            else              { cbp[c >> 1] += cbv; crp[c >> 1] += crv; }
        }
        float4 R1 = *(const float4*)(base + 4);
        float4 G1 = *(const float4*)(base + plane + 4);
        float4 B1 = *(const float4*)(base + 2 * plane + 4);
        float Rb[4] = {R1.x, R1.y, R1.z, R1.w};
        float Gb[4] = {G1.x, G1.y, G1.z, G1.w};
        float Bb[4] = {B1.x, B1.y, B1.z, B1.w};
        #pragma unroll
        for (int c = 0; c < 4; c++) {
            float rr = Rb[c] * 255.f, gg = Gb[c] * 255.f, bb = Bb[c] * 255.f;
            y[4 + c] = 0.299f * rr + 0.587f * gg + 0.114f * bb - 128.f;
            float cbv = -0.168736f * rr - 0.331264f * gg + 0.5f      * bb;
            float crv =  0.5f      * rr - 0.418688f * gg - 0.081312f * bb;
            if ((c & 1) == 0) { cbp[2 + (c >> 1)] = cbv;  crp[2 + (c >> 1)] = crv; }
            else              { cbp[2 + (c >> 1)] += cbv; crp[2 + (c >> 1)] += crv; }
        }
    }
    // vertical 2x2 pairing: rows r, r^1 are lanes t, t^8 (same warp)
    #pragma unroll
    for (int k = 0; k < 4; k++) {
        cbp[k] += __shfl_xor_sync(0xFFFFFFFFu, cbp[k], 8);
        crp[k] += __shfl_xor_sync(0xFFFFFFFFu, crp[k], 8);
    }
    // horizontal gather: lane t <-> t^1 (sx^1) to assemble full 8-col rows
    float cbe[4], cre[4];
    #pragma unroll
    for (int k = 0; k < 4; k++) {
        cbe[k] = __shfl_xor_sync(0xFFFFFFFFu, cbp[k], 1);
        cre[k] = __shfl_xor_sync(0xFFFFFFFFu, crp[k], 1);
    }
    if (((row & 1) | (sx & 1)) == 0) {
        // this thread owns one full chroma row of block cbB (and cbB+4 for Cr)
        int cbB = sx >> 1, cr_ = row >> 1;
        float rowc[8] = {cbp[0]*0.25f, cbp[1]*0.25f, cbp[2]*0.25f, cbp[3]*0.25f,
                         cbe[0]*0.25f, cbe[1]*0.25f, cbe[2]*0.25f, cbe[3]*0.25f};
        float a[8];
        dct8_fwd(rowc, a);               // chroma row-DCT in regs
        #pragma unroll
        for (int v = 0; v < 8; v++) sC[cbB * 72 + cr_ * 9 + v] = a[v];  // sw=0
        float rowr[8] = {crp[0]*0.25f, crp[1]*0.25f, crp[2]*0.25f, crp[3]*0.25f,
                         cre[0]*0.25f, cre[1]*0.25f, cre[2]*0.25f, cre[3]*0.25f};
        dct8_fwd(rowr, a);
        #pragma unroll
        for (int v = 0; v < 8; v++)
            sC[(cbB + 4) * 72 + cr_ * 9 + (v ^ 4)] = a[v];              // sw=4
    }
    {
        float a[8];
        dct8_fwd(y, a);                  // Y row-DCT in regs
        #pragma unroll
        for (int v = 0; v < 8; v++) sY[ybase + (v ^ ysw)] = a[v];
    }
    __syncthreads();

    // ---- E2: Y column pass in place — 128 tasks, perfectly balanced.
    {
        int b = t >> 3, v = t & 7;
        int cbase = b * 72 + (v ^ (b & 4));
        float col[8];
        #pragma unroll
        for (int x = 0; x < 8; x++) col[x] = sY[cbase + x * 9];
        float cf[8];
        dct8_fwd(col, cf);

        const float4 qa0 = *(const float4*)&sAqTY[v * 8];
        const float4 qa1 = *(const float4*)&sAqTY[v * 8 + 4];
        const float4 qb0 = *(const float4*)&sBqTY[v * 8];
        const float4 qb1 = *(const float4*)&sBqTY[v * 8 + 4];
        const float Aq[8] = {qa0.x, qa0.y, qa0.z, qa0.w, qa1.x, qa1.y, qa1.z, qa1.w};
        const float Bq[8] = {qb0.x, qb0.y, qb0.z, qb0.w, qb1.x, qb1.y, qb1.z, qb1.w};
        float h[8];
        #pragma unroll
        for (int u = 0; u < 8; u++) {
            float c = cf[u] * Aq[u];
            float r = rintf(c);          // round-half-even == jnp.round
            float d = c - r;
            h[u] = (r + d * d * d) * Bq[u];
        }
        float hw[8];
        dct8_inv(h, hw);
        #pragma unroll
        for (int x = 0; x < 8; x++) sY[cbase + x * 9] = hw[x];
    }
    __syncthreads();

    // ---- E3: chroma column pass in place (64 tasks).
    if (t < 64) {
        int b = t >> 3, v = t & 7;
        int cbase = b * 72 + (v ^ (b & 4));
        float col[8];
        #pragma unroll
        for (int x = 0; x < 8; x++) col[x] = sC[cbase + x * 9];
        float cf[8];
        dct8_fwd(col, cf);

        const float4 qa0 = *(const float4*)&sAqTC[v * 8];
        const float4 qa1 = *(const float4*)&sAqTC[v * 8 + 4];
        const float4 qb0 = *(const float4*)&sBqTC[v * 8];
        const float4 qb1 = *(const float4*)&sBqTC[v * 8 + 4];
        const float Aq[8] = {qa0.x, qa0.y, qa0.z, qa0.w, qa1.x, qa1.y, qa1.z, qa1.w};
        const float Bq[8] = {qb0.x, qb0.y, qb0.z, qb0.w, qb1.x, qb1.y, qb1.z, qb1.w};
        float h[8];
        #pragma unroll
        for (int u = 0; u < 8; u++) {
            float c = cf[u] * Aq[u];
            float r = rintf(c);
            float d = c - r;
            h[u] = (r + d * d * d) * Bq[u];
        }
        float hw[8];
        dct8_inv(h, hw);
        #pragma unroll
        for (int x = 0; x < 8; x++) sC[cbase + x * 9] = hw[x];
    }
    __syncthreads();

    // ---- E4: chroma row-inverse, in place per-row (64 tasks).
    if (t < 64) {
        int b = t >> 3, r = t & 7;
        int rb = b * 72 + r * 9, sw = b & 4;
        float hv[8];
        #pragma unroll
        for (int v = 0; v < 8; v++) hv[v] = sC[rb + (v ^ sw)];
        float p[8];
        dct8_inv(hv, p);
        #pragma unroll
        for (int j = 0; j < 8; j++) sC[rb + j] = p[j];
    }
    __syncthreads();

    // ---- E5: Y inverse row-DCT in regs, chroma read, YCbCr->RGB, store.
    float yp[8];
    {
        float hv[8];
        #pragma unroll
        for (int v = 0; v < 8; v++) hv[v] = sY[ybase + (v ^ ysw)];
        dct8_inv(hv, yp);
    }
    float cbq[4], crq[4];
    {
        int cbB = sx >> 1, c0 = (sx & 1) * 4, cr_ = row >> 1;
        #pragma unroll
        for (int k = 0; k < 4; k++) {
            cbq[k] = sC[cbB * 72       + cr_ * 9 + c0 + k];
            crq[k] = sC[(cbB + 4) * 72 + cr_ * 9 + c0 + k];
        }
    }
    float* op = out + (size_t)bimg * 3 * plane + (size_t)py0 * IMG + px0;
    #pragma unroll
    for (int h = 0; h < 2; h++) {        // two float4 groups, short live ranges
        float Rv[4], Gv[4], Bv[4];
        #pragma unroll
        for (int c = 0; c < 4; c++) {
            int cc = h * 4 + c;
            float yy = yp[cc] + 128.f;
            float cb = cbq[cc >> 1];
            float cr = crq[cc >> 1];
            float rr = yy + 1.402f * cr;
            float gg = yy - 0.344136f * cb - 0.714136f * cr;
            float bb = yy + 1.772f * cb;
            Rv[c] = fminf(fmaxf(rr, 0.f), 255.f) * (1.f / 255.f);
            Gv[c] = fminf(fmaxf(gg, 0.f), 255.f) * (1.f / 255.f);
            Bv[c] = fminf(fmaxf(bb, 0.f), 255.f) * (1.f / 255.f);
        }
        *(float4*)(op + h * 4)             = make_float4(Rv[0], Rv[1], Rv[2], Rv[3]);
        *(float4*)(op + plane + h * 4)     = make_float4(Gv[0], Gv[1], Gv[2], Gv[3]);
        *(float4*)(op + 2 * plane + h * 4) = make_float4(Bv[0], Bv[1], Bv[2], Bv[3]);
    }
}

extern "C" void kernel_launch(void* const* d_in, const int* in_sizes, int n_in,
                              void* d_out, int out_size) {
    const float* img = (const float*)d_in[0];
    float* out = (float*)d_out;
    int batch = in_sizes[0] / (3 * IMG * IMG);        // 32
    int tiles = batch * (IMG / 16) * (IMG / 64);      // 32 * 32 * 8 = 8192
    jpeg_tile_kernel<<<tiles, 128>>>(img, out);
}

// round 11
// speedup vs baseline: 1.1343x; 1.1343x over previous
#include <cuda_runtime.h>
#include <math.h>

// ---------------------------------------------------------------------------
// Differentiable JPEG (quality 80) forward pass, fused single kernel.
// Tile = 32x16 px, CTA = 128 threads; each thread owns a 1x4 row segment.
// Global I/O: float4 (LDG.128/STG.128, 16B-aligned). Shared staging: SCALAR
// on the proven [8][9] layout (36B row pitch is not float4-alignable).
// Stage pipeline identical to the best-known R5 structure.
// Chroma 2x2 average: in-thread horizontal + shfl_xor(8) vertical pairing.
// ---------------------------------------------------------------------------

#define IMG 512

__constant__ float c_YTAB[64] = {
    16,11,10,16,24,40,51,61,  12,12,14,19,26,58,60,55,
    14,13,16,24,40,57,69,56,  14,17,22,29,51,87,80,62,
    18,22,37,56,68,109,103,77, 24,35,55,64,81,104,113,92,
    49,64,78,87,103,121,120,101, 72,92,95,98,112,100,103,99};
__constant__ float c_CTAB[64] = {
    17,18,24,47,99,99,99,99,  18,21,26,66,99,99,99,99,
    24,26,56,99,99,99,99,99,  47,66,99,99,99,99,99,99,
    99,99,99,99,99,99,99,99,  99,99,99,99,99,99,99,99,
    99,99,99,99,99,99,99,99,  99,99,99,99,99,99,99,99};

// cos(k*pi/16)
#define C1 0.980785280403230449f
#define C2 0.923879532511286756f
#define C3 0.831469612302545237f
#define C4 0.707106781186547524f
#define C5 0.555570233019602225f
#define C6 0.382683432365089772f
#define C7 0.195090322016128268f

__device__ __forceinline__ void dct8_fwd(const float in[8], float a[8]) {
    float s0 = in[0] + in[7], s1 = in[1] + in[6];
    float s2 = in[2] + in[5], s3 = in[3] + in[4];
    float d0 = in[0] - in[7], d1 = in[1] - in[6];
    float d2 = in[2] - in[5], d3 = in[3] - in[4];
    a[0] = (s0 + s3) + (s1 + s2);
    a[2] = C2 * s0 + C6 * s1 - C6 * s2 - C2 * s3;
    a[4] = C4 * ((s0 + s3) - (s1 + s2));
    a[6] = C6 * s0 - C2 * s1 + C2 * s2 - C6 * s3;
    a[1] = C1 * d0 + C3 * d1 + C5 * d2 + C7 * d3;
    a[3] = C3 * d0 - C7 * d1 - C1 * d2 - C5 * d3;
    a[5] = C5 * d0 - C1 * d1 + C7 * d2 + C3 * d3;
    a[7] = C7 * d0 - C5 * d1 + C3 * d2 - C1 * d3;
}

__device__ __forceinline__ void dct8_inv(const float h[8], float p[8]) {
    float e0 = h[0] + C2 * h[2] + C4 * h[4] + C6 * h[6];
    float e1 = h[0] + C6 * h[2] - C4 * h[4] - C2 * h[6];
    float e2 = h[0] - C6 * h[2] - C4 * h[4] + C2 * h[6];
    float e3 = h[0] - C2 * h[2] + C4 * h[4] - C6 * h[6];
    float o0 = C1 * h[1] + C3 * h[3] + C5 * h[5] + C7 * h[7];
    float o1 = C3 * h[1] - C7 * h[3] - C1 * h[5] - C5 * h[7];
    float o2 = C5 * h[1] - C1 * h[3] + C7 * h[5] + C3 * h[7];
    float o3 = C7 * h[1] - C5 * h[3] + C3 * h[5] - C1 * h[7];
    p[0] = e0 + o0;  p[7] = e0 - o0;
    p[1] = e1 + o1;  p[6] = e1 - o1;
    p[2] = e2 + o2;  p[5] = e2 - o2;
    p[3] = e3 + o3;  p[4] = e3 - o3;
}

__global__ void __launch_bounds__(128)
jpeg_tile_kernel(const float* __restrict__ img, float* __restrict__ out) {
    __shared__ float sAq[2][64];     // (ALPHA*0.25)/q
    __shared__ float sBq[2][64];     // (ALPHA*0.25)*q
    __shared__ float s1[12][8][9];   // blocks 0..7 = Y, 8..9 = Cb, 10..11 = Cr
    __shared__ float s2[12][8][9];

    const int t = threadIdx.x;

    if (t < 64) {
        int u = t >> 3, v = t & 7;
        float au = (u == 0) ? 0.70710678118654752f : 1.f;
        float av = (v == 0) ? 0.70710678118654752f : 1.f;
        float S = au * av * 0.25f;
        float qy = c_YTAB[t] * 0.4f;   // QUALITY=80 -> FACTOR=0.4
        float qc = c_CTAB[t] * 0.4f;
        sAq[0][t] = __fdividef(S, qy);  sBq[0][t] = S * qy;
        sAq[1][t] = __fdividef(S, qc);  sBq[1][t] = S * qc;
    }

    const int tile = blockIdx.x;
    const int tx   = tile & 15;          // 16 tiles across (32 px each)
    const int ty   = (tile >> 4) & 31;   // 32 tiles down (16 px each)
    const int bimg = tile >> 9;

    const int c = t & 7;                 // 4-px group 0..7 (32 px across)
    const int r = t >> 3;                // tile row 0..15
    const int px0 = tx * 32 + c * 4;
    const int py  = ty * 16 + r;

    const size_t plane = (size_t)IMG * IMG;
    const float* base = img + (size_t)bimg * 3 * plane + (size_t)py * IMG + px0;

    // Y block / position for this segment
    const int yblk = ((r >> 3) << 2) + (c >> 1);    // 4 across x 2 down
    const int ycol = (c & 1) * 4;
    const int yrow = r & 7;
    // Chroma block/col for this segment's 2 averaged px
    const int cbB  = c >> 2;                        // 0..1
    const int ccol = (c * 2) & 7;                   // 0,2,4,6 pattern
    const int crow = r >> 1;

    // ---- Pixel phase: float4 RGB loads, color-convert, scalar staging.
    float4 Rv4 = *(const float4*)(base);
    float4 Gv4 = *(const float4*)(base + plane);
    float4 Bv4 = *(const float4*)(base + 2 * plane);
    float Ra[4] = {Rv4.x, Rv4.y, Rv4.z, Rv4.w};
    float Ga[4] = {Gv4.x, Gv4.y, Gv4.z, Gv4.w};
    float Ba[4] = {Bv4.x, Bv4.y, Bv4.z, Bv4.w};

    float y4[4], cbp[2], crp[2];
    #pragma unroll
    for (int k = 0; k < 4; k++) {
        float rr = Ra[k] * 255.f, gg = Ga[k] * 255.f, bb = Ba[k] * 255.f;
        y4[k] = 0.299f * rr + 0.587f * gg + 0.114f * bb - 128.f;  // -128 folded
        float cbv = -0.168736f * rr - 0.331264f * gg + 0.5f      * bb;
        float crv =  0.5f      * rr - 0.418688f * gg - 0.081312f * bb;
        if ((k & 1) == 0) { cbp[k >> 1] = cbv;  crp[k >> 1] = crv; }
        else              { cbp[k >> 1] += cbv; crp[k >> 1] += crv; }
    }
    // vertical pair: rows r, r^1 are lanes t, t^8 (same warp)
    #pragma unroll
    for (int k = 0; k < 2; k++) {
        cbp[k] += __shfl_xor_sync(0xFFFFFFFFu, cbp[k], 8);
        crp[k] += __shfl_xor_sync(0xFFFFFFFFu, crp[k], 8);
    }
    #pragma unroll
    for (int k = 0; k < 4; k++) s1[yblk][yrow][ycol + k] = y4[k];
    if ((r & 1) == 0) {
        #pragma unroll
        for (int k = 0; k < 2; k++) {
            s1[8  + cbB][crow][ccol + k] = cbp[k] * 0.25f;
            s1[10 + cbB][crow][ccol + k] = crp[k] * 0.25f;
        }
    }
    __syncthreads();

    // ---- Stage A: vertical DCT: s2[b][u][j] = sum_x CT[x][u]*s1[b][x][j]
    if (t < 96) {
        int blk = t >> 3, j = t & 7;
        float in[8], a[8];
        #pragma unroll
        for (int x = 0; x < 8; x++) in[x] = s1[blk][x][j];
        dct8_fwd(in, a);
        #pragma unroll
        for (int u = 0; u < 8; u++) s2[blk][u][j] = a[u];
    }
    __syncthreads();

    // ---- Stage B: horizontal DCT + diff_round quant + horizontal IDCT.
    if (t < 96) {
        int blk = t >> 3, u = t & 7;
        int ti = (blk < 8) ? 0 : 1;
        float row[8], cv[8];
        #pragma unroll
        for (int y = 0; y < 8; y++) row[y] = s2[blk][u][y];
        dct8_fwd(row, cv);

        const float4 qa0 = *(const float4*)&sAq[ti][u * 8];
        const float4 qa1 = *(const float4*)&sAq[ti][u * 8 + 4];
        const float4 qb0 = *(const float4*)&sBq[ti][u * 8];
        const float4 qb1 = *(const float4*)&sBq[ti][u * 8 + 4];
        const float Aq[8]  = {qa0.x, qa0.y, qa0.z, qa0.w, qa1.x, qa1.y, qa1.z, qa1.w};
        const float Bq2[8] = {qb0.x, qb0.y, qb0.z, qb0.w, qb1.x, qb1.y, qb1.z, qb1.w};

        float h[8];
        #pragma unroll
        for (int v = 0; v < 8; v++) {
            float cc = cv[v] * Aq[v];
            float rr = rintf(cc);             // round-half-even == jnp.round
            float dd = cc - rr;
            h[v] = (rr + dd * dd * dd) * Bq2[v];
        }
        float p[8];
        dct8_inv(h, p);
        #pragma unroll
        for (int y = 0; y < 8; y++) s1[blk][u][y] = p[y];
    }
    __syncthreads();

    // ---- Stage C: vertical IDCT: s2[b][x][j] = sum_u CT[x][u]*s1[b][u][j]
    if (t < 96) {
        int blk = t >> 3, j = t & 7;
        float in[8], p[8];
        #pragma unroll
        for (int u = 0; u < 8; u++) in[u] = s1[blk][u][j];
        dct8_inv(in, p);
        float add = (blk < 8) ? 128.f : 0.f;   // chroma +128/-128 cancels
        #pragma unroll
        for (int x = 0; x < 8; x++) s2[blk][x][j] = p[x] + add;
    }
    __syncthreads();

    // ---- Writeback: scalar shared reads, YCbCr->RGB, clip, float4 stores.
    float yv[4], cbv2[2], crv2[2];
    #pragma unroll
    for (int k = 0; k < 4; k++) yv[k] = s2[yblk][yrow][ycol + k];
    #pragma unroll
    for (int k = 0; k < 2; k++) {
        cbv2[k] = s2[8  + cbB][crow][ccol + k];
        crv2[k] = s2[10 + cbB][crow][ccol + k];
    }

    float Ro[4], Go[4], Bo[4];
    #pragma unroll
    for (int k = 0; k < 4; k++) {
        float yy = yv[k];
        float cb = cbv2[k >> 1];
        float cr = crv2[k >> 1];
        float rr = yy + 1.402f * cr;
        float gg = yy - 0.344136f * cb - 0.714136f * cr;
        float bb = yy + 1.772f * cb;
        Ro[k] = fminf(fmaxf(rr, 0.f), 255.f) * (1.f / 255.f);
        Go[k] = fminf(fmaxf(gg, 0.f), 255.f) * (1.f / 255.f);
        Bo[k] = fminf(fmaxf(bb, 0.f), 255.f) * (1.f / 255.f);
    }
    float* op = out + (size_t)bimg * 3 * plane + (size_t)py * IMG + px0;
    *(float4*)(op)             = make_float4(Ro[0], Ro[1], Ro[2], Ro[3]);
    *(float4*)(op + plane)     = make_float4(Go[0], Go[1], Go[2], Go[3]);
    *(float4*)(op + 2 * plane) = make_float4(Bo[0], Bo[1], Bo[2], Bo[3]);
}

extern "C" void kernel_launch(void* const* d_in, const int* in_sizes, int n_in,
                              void* d_out, int out_size) {
    const float* img = (const float*)d_in[0];
    float* out = (float*)d_out;
    int batch = in_sizes[0] / (3 * IMG * IMG);         // 32
    int tiles = batch * (IMG / 16) * (IMG / 32);       // 16384
    jpeg_tile_kernel<<<tiles, 128>>>(img, out);
}